// round 14
// baseline (speedup 1.0000x reference)
#include <cuda_runtime.h>
#include <cuda_fp16.h>
#include <stdint.h>
#include <math.h>

#define BDIM   4
#define NTOK   2048
#define FEATC  256
#define HIDC   256
#define NHEADS 4
#define DHEAD  64
#define MROWS  (BDIM*NTOK)
#define QK_SCALE_L2 0.424660902f   // DH^-0.25 * sqrt(log2 e)

// ---------------- scratch ----------------
__device__ __half g_qk0[MROWS*HIDC];
__device__ __half g_qk1[MROWS*HIDC];
__device__ __half g_v0 [MROWS*HIDC];
__device__ __half g_v1 [MROWS*HIDC];
__device__ __half g_cat0[MROWS*2*FEATC];   // [x fp16 | m fp16]
__device__ __half g_cat1[MROWS*2*FEATC];
__device__ float  g_h0 [MROWS*2*FEATC];
__device__ float  g_h1 [MROWS*2*FEATC];
__device__ __half g_hg0[MROWS*2*FEATC];
__device__ __half g_hg1[MROWS*2*FEATC];
__device__ __half g_wqk[HIDC*FEATC];
__device__ __half g_wv [HIDC*FEATC];
__device__ __half g_wpT[HIDC*HIDC];          // Wp transposed [in][out]
__device__ __half g_w1p[2*FEATC*HIDC];       // W1 cols 256:512
__device__ __half g_wcat[2*FEATC*2*FEATC];   // [W1x | W1m]
__device__ __half g_w2 [FEATC*2*FEATC];
__device__ float  g_b1p[2*FEATC];            // b1 + W1p @ bp
__device__ float  g_zeros[256];              // never written (zero-init)

#define EPI_HEAD_H  0
#define EPI_PLAIN_H 1
#define EPI_PLAIN_F 2
#define EPI_RES     3

// ---------------- asm helpers ----------------
__device__ __forceinline__ void mma_f16(float* d, const unsigned* a, const unsigned* b) {
    asm volatile(
        "mma.sync.aligned.m16n8k16.row.col.f32.f16.f16.f32 "
        "{%0,%1,%2,%3}, {%4,%5,%6,%7}, {%8,%9}, {%0,%1,%2,%3};\n"
        : "+f"(d[0]), "+f"(d[1]), "+f"(d[2]), "+f"(d[3])
        : "r"(a[0]), "r"(a[1]), "r"(a[2]), "r"(a[3]), "r"(b[0]), "r"(b[1]));
}
// d = a*b + 0  (no accumulator read)
__device__ __forceinline__ void mma_f16_z(float* d, const unsigned* a, const unsigned* b) {
    asm volatile(
        "mma.sync.aligned.m16n8k16.row.col.f32.f16.f16.f32 "
        "{%0,%1,%2,%3}, {%4,%5,%6,%7}, {%8,%9}, {%10,%11,%12,%13};\n"
        : "=f"(d[0]), "=f"(d[1]), "=f"(d[2]), "=f"(d[3])
        : "r"(a[0]), "r"(a[1]), "r"(a[2]), "r"(a[3]), "r"(b[0]), "r"(b[1]),
          "f"(0.f), "f"(0.f), "f"(0.f), "f"(0.f));
}
__device__ __forceinline__ void ldsm4(unsigned* r, uint32_t a) {
    asm volatile("ldmatrix.sync.aligned.m8n8.x4.shared.b16 {%0,%1,%2,%3}, [%4];"
        : "=r"(r[0]), "=r"(r[1]), "=r"(r[2]), "=r"(r[3]) : "r"(a));
}
__device__ __forceinline__ void ldsm4t(unsigned* r, uint32_t a) {
    asm volatile("ldmatrix.sync.aligned.m8n8.x4.trans.shared.b16 {%0,%1,%2,%3}, [%4];"
        : "=r"(r[0]), "=r"(r[1]), "=r"(r[2]), "=r"(r[3]) : "r"(a));
}
__device__ __forceinline__ void cpa16(uint32_t dst, const void* src) {
    asm volatile("cp.async.cg.shared.global [%0], [%1], 16;" :: "r"(dst), "l"(src));
}
__device__ __forceinline__ void cp_commit() { asm volatile("cp.async.commit_group;"); }
__device__ __forceinline__ void cp_wait1() { asm volatile("cp.async.wait_group 1;"); }

__device__ __forceinline__ unsigned h2u(float x, float y) {
    __half2 h = __floats2half2_rn(x, y);
    return *reinterpret_cast<unsigned*>(&h);
}
__device__ __forceinline__ unsigned ex2h2(float x, float y) {
    __half2 h = __floats2half2_rn(x, y);
    unsigned u = *reinterpret_cast<unsigned*>(&h), r;
    asm volatile("ex2.approx.f16x2 %0, %1;" : "=r"(r) : "r"(u));
    return r;
}

// ---------------------------------------------------------------------------
// fp32 -> fp16 conversions; Wp transposed; W1 split into [W1x -> wcat | w1p]
// ---------------------------------------------------------------------------
__global__ __launch_bounds__(256) void convert_kernel(
    const float* __restrict__ x0, const float* __restrict__ x1,
    __half* __restrict__ cat0, __half* __restrict__ cat1,
    const float* __restrict__ Wqk, const float* __restrict__ Wv,
    const float* __restrict__ Wp, const float* __restrict__ W1, const float* __restrict__ W2,
    __half* __restrict__ wqk, __half* __restrict__ wv, __half* __restrict__ wpT,
    __half* __restrict__ w1p, __half* __restrict__ wcat, __half* __restrict__ w2)
{
    const int z = blockIdx.z;
    const long idx = (long)blockIdx.x * 256 + threadIdx.x;   // float4 units
    const float* src = nullptr; long cnt = 0;
    switch (z) {
        case 0: src = x0;  cnt = MROWS*FEATC/4; break;
        case 1: src = x1;  cnt = MROWS*FEATC/4; break;
        case 2: src = Wqk; cnt = HIDC*FEATC/4; break;
        case 3: src = Wv;  cnt = HIDC*FEATC/4; break;
        case 4: src = Wp;  cnt = HIDC*HIDC/4; break;
        case 5: src = W1;  cnt = 2*FEATC*512/4; break;
        case 6: src = W2;  cnt = FEATC*2*FEATC/4; break;
    }
    if (idx >= cnt) return;
    float4 v = *(const float4*)(src + idx*4);
    uint2 u; u.x = h2u(v.x, v.y); u.y = h2u(v.z, v.w);
    if (z <= 1) {
        __half* dst = z ? cat1 : cat0;
        long row = idx >> 6, c = (idx & 63) * 4;
        *(uint2*)(dst + row * 512 + c) = u;
    } else if (z == 2) {
        *(uint2*)(wqk + idx*4) = u;
    } else if (z == 3) {
        *(uint2*)(wv + idx*4) = u;
    } else if (z == 4) {
        long k = idx >> 6, i0 = (idx & 63) * 4;
        wpT[(i0+0)*HIDC + k] = __float2half_rn(v.x);
        wpT[(i0+1)*HIDC + k] = __float2half_rn(v.y);
        wpT[(i0+2)*HIDC + k] = __float2half_rn(v.z);
        wpT[(i0+3)*HIDC + k] = __float2half_rn(v.w);
    } else if (z == 5) {
        long o = idx >> 7, c = (idx & 127) * 4;
        if (c < 256) *(uint2*)(wcat + o * 512 + c) = u;
        else         *(uint2*)(w1p  + o * 256 + (c - 256)) = u;
    } else {
        *(uint2*)(w2 + idx*4) = u;
    }
}

// b1p[o] = b1[o] + sum_k W1[o][256+k] * bp[k]
__global__ __launch_bounds__(32) void b1p_kernel(
    const float* __restrict__ W1, const float* __restrict__ bp,
    const float* __restrict__ b1, float* __restrict__ b1p)
{
    const int o = blockIdx.x, lane = threadIdx.x;
    float s = 0.f;
#pragma unroll
    for (int i = 0; i < 8; i++) {
        int k = lane + i * 32;
        s += W1[(size_t)o * 512 + 256 + k] * bp[k];
    }
#pragma unroll
    for (int off = 16; off > 0; off >>= 1) s += __shfl_xor_sync(0xffffffffu, s, off);
    if (lane == 0) b1p[o] = b1[o] + s;
}

// ---------------------------------------------------------------------------
// GEMM: C = epi( A[M,K] @ W[N,K]^T + b ), fp16 in, fp32 acc.
// 3-stage cp.async ring, K-chunk 64. Tile 128x128x64; warp tile 32x64.
// (R11-R13 version, verbatim)
// ---------------------------------------------------------------------------
#define GLD  36
#define SST_W (256*GLD)
#define GEMM_SMEM (3*SST_W*4)         // 110592 B
__global__ __launch_bounds__(256, 2) void gemm_kernel(
    const __half* __restrict__ A0, const __half* __restrict__ A1, int lda,
    const __half* __restrict__ Wa, const float* __restrict__ biasa,
    const __half* __restrict__ Wb, const float* __restrict__ biasb,
    void* C0v, void* C1v, void* Cb0v, void* Cb1v, int ldc, int coloff,
    const float* __restrict__ R0, const float* __restrict__ R1,
    int K, int ytiles, int epi, float scalea, float scaleb)
{
    extern __shared__ unsigned sm[];
    const int t = threadIdx.x, lane = t & 31, wid = t >> 5;
    const int g = lane >> 2, q = lane & 3;
    const int wm = wid >> 1, wn = wid & 1;
    const int z = blockIdx.z;
    const bool second = (int)blockIdx.y >= ytiles;
    const int yy = second ? (blockIdx.y - ytiles) : blockIdx.y;
    const int m0g = blockIdx.x * 128, n0g = yy * 128;
    const __half* A = z ? A1 : A0;
    const __half* W = second ? Wb : Wa;
    const float* bias = second ? biasb : biasa;
    const float scale = second ? scaleb : scalea;
    void* Cv = second ? (z ? Cb1v : Cb0v) : (z ? C1v : C0v);
    const float* R = z ? R1 : R0;

    const uint32_t sb = (uint32_t)__cvta_generic_to_shared(sm);
    const uint32_t aoff = (((lane & 15) * GLD) + ((lane >> 4) << 2)) * 4;
    const uint32_t boff = (((lane & 7) + ((lane >> 4) << 3)) * GLD + (((lane >> 3) & 1) << 2)) * 4;

    const int nk = K >> 6;
    auto issue = [&](int kt) {
        const uint32_t stb = sb + (uint32_t)((kt % 3) * SST_W) * 4;
        const int kc = kt << 6;
#pragma unroll
        for (int i = 0; i < 8; i++) {
            const int idx = t + i * 256;
            const int row = idx >> 3, c = idx & 7;
            const uint32_t dst = stb + (uint32_t)(row * GLD + c * 4) * 4;
            const __half* src = (row < 128)
                ? (A + (size_t)(m0g + row) * lda + kc + c*8)
                : (W + (size_t)(n0g + row - 128) * K + kc + c*8);
            cpa16(dst, src);
        }
    };

    float acc[2][8][4];
#pragma unroll
    for (int mt = 0; mt < 2; mt++)
#pragma unroll
        for (int nt = 0; nt < 8; nt++)
#pragma unroll
            for (int i = 0; i < 4; i++) acc[mt][nt][i] = 0.f;

    issue(0); cp_commit();
    issue(1); cp_commit();

    for (int kt = 0; kt < nk; kt++) {
        cp_wait1();
        __syncthreads();
        if (kt + 2 < nk) issue(kt + 2);
        cp_commit();
        const uint32_t stb = sb + (uint32_t)((kt % 3) * SST_W) * 4;
#pragma unroll
        for (int ch = 0; ch < 4; ch++) {
            unsigned a[2][4], b[4][4];
#pragma unroll
            for (int mt = 0; mt < 2; mt++)
                ldsm4(a[mt], stb + (uint32_t)(((wm*32 + mt*16)*GLD + ch*8) * 4) + aoff);
#pragma unroll
            for (int bt = 0; bt < 4; bt++)
                ldsm4(b[bt], stb + (uint32_t)(((128 + wn*64 + bt*16)*GLD + ch*8) * 4) + boff);
#pragma unroll
            for (int mt = 0; mt < 2; mt++)
#pragma unroll
                for (int bt = 0; bt < 4; bt++) {
                    mma_f16(acc[mt][2*bt + 0], a[mt], b[bt] + 0);
                    mma_f16(acc[mt][2*bt + 1], a[mt], b[bt] + 2);
                }
        }
    }

#pragma unroll
    for (int mt = 0; mt < 2; mt++) {
#pragma unroll
        for (int nt = 0; nt < 8; nt++) {
            const int row = m0g + wm*32 + mt*16 + g;
            const int col = n0g + wn*64 + nt*8 + 2*q;
            const float b0 = bias[col], b1 = bias[col + 1];
#pragma unroll
            for (int hh = 0; hh < 2; hh++) {
                const int rr = row + hh * 8;
                float vx = (acc[mt][nt][hh*2+0] + b0) * scale;
                float vy = (acc[mt][nt][hh*2+1] + b1) * scale;
                if (epi == EPI_HEAD_H) {
                    const int b_ = rr >> 11, nn = rr & (NTOK - 1);
                    const int h_ = col >> 6, dd = col & 63;
                    __half2 hv = __floats2half2_rn(vx, vy);
                    *(__half2*)((__half*)Cv + (((size_t)(b_*NHEADS + h_))*NTOK + nn)*DHEAD + dd) = hv;
                } else if (epi == EPI_PLAIN_H) {
                    __half2 hv = __floats2half2_rn(vx, vy);
                    *(__half2*)((__half*)Cv + (size_t)rr * ldc + coloff + col) = hv;
                } else if (epi == EPI_RES) {
                    float2 rv = *(const float2*)&R[(size_t)rr * ldc + col];
                    float2 v2; v2.x = vx + rv.x; v2.y = vy + rv.y;
                    *(float2*)((float*)Cv + (size_t)rr * ldc + col) = v2;
                } else {
                    float2 v2; v2.x = vx; v2.y = vy;
                    *(float2*)((float*)Cv + (size_t)rr * ldc + col) = v2;
                }
            }
        }
    }
}

// ---------------------------------------------------------------------------
// Flash attention, fixed-reference softmax, ntp-level software pipelining:
// S-MMA for group ntp+1 is issued BEFORE the PV of group ntp, so the tensor
// queue stays full through the scalar exp/CVT phase.
// KV tile 128 j/stage, Q staged via ring slot 2. Output into cat[:, 256:].
// ---------------------------------------------------------------------------
#define ALD  36
#define AST_W (256*ALD)
#define ATT_SMEM (3*AST_W*4)            // 110592 B

__global__ __launch_bounds__(256, 2) void attn_kernel(
    const __half* __restrict__ qk0, const __half* __restrict__ qk1,
    const __half* __restrict__ v0,  const __half* __restrict__ v1,
    __half* __restrict__ O0, __half* __restrict__ O1, int ldo)
{
    extern __shared__ unsigned smw[];

    const __half *Q, *Kp, *Vp; __half* O;
    if (blockIdx.z == 0) { Q = qk0; Kp = qk1; Vp = v1; O = O0; }
    else                 { Q = qk1; Kp = qk0; Vp = v0; O = O1; }

    const int bh = blockIdx.y;
    const int i0 = blockIdx.x * 128;
    const __half* Qb = Q  + (size_t)bh * NTOK * DHEAD;
    const __half* Kb = Kp + (size_t)bh * NTOK * DHEAD;
    const __half* Vb = Vp + (size_t)bh * NTOK * DHEAD;

    const int t = threadIdx.x, lane = t & 31, wid = t >> 5;
    const int g = lane >> 2, q = lane & 3;
    const int wrow = wid * 16;

    const uint32_t sbase = (uint32_t)__cvta_generic_to_shared(smw);
    const uint32_t aoffA = (((lane & 15) * ALD) + ((lane >> 4) << 2)) * 4;
    const uint32_t boffA = (((lane & 7) + ((lane >> 4) << 3)) * ALD + (((lane >> 3) & 1) << 2)) * 4;
    const uint32_t voffA = ((lane & 15) * ALD) * 4 + ((lane >> 4) << 4);

    const int kvrow = t >> 3, kvch = t & 7;
    auto issue = [&](int jt) {
        const uint32_t stb = sbase + (uint32_t)((jt % 3) * AST_W) * 4;
        const int j0 = jt << 7;
#pragma unroll
        for (int i = 0; i < 8; i++) {
            const int idx = kvrow + i * 32;
            const __half* src = (idx < 128)
                ? (Kb + (size_t)(j0 + idx) * DHEAD + kvch*8)
                : (Vb + (size_t)(j0 + idx - 128) * DHEAD + kvch*8);
            cpa16(stb + (uint32_t)(idx*ALD + kvch*4)*4, src);
        }
    };

    issue(0); cp_commit();
    issue(1); cp_commit();

    // stage Q tile through ring slot 2
#pragma unroll
    for (int i = 0; i < 4; i++) {
        int id = t + i * 256;
        int row = id >> 3, c8 = (id & 7) * 8;
        uint4 u = *(const uint4*)(Qb + (size_t)(i0 + row) * DHEAD + c8);
        *(uint4*)&smw[2*AST_W + row * ALD + (c8 >> 1)] = u;
    }
    __syncthreads();
    unsigned qf[4][4];
#pragma unroll
    for (int ks = 0; ks < 4; ks++)
        ldsm4(qf[ks], sbase + (uint32_t)((2*AST_W + wrow * ALD + ks * 8) * 4) + aoffA);

    float o[8][4];
#pragma unroll
    for (int dt = 0; dt < 8; dt++)
#pragma unroll
        for (int i = 0; i < 4; i++) o[dt][i] = 0.f;
    float rm0 = 0.f, rm1 = 0.f;              // fixed softmax reference
    float rsum[4] = {0.f, 0.f, 0.f, 0.f};    // persistent P@ones accumulator

    const unsigned bones[2] = {0x3C003C00u, 0x3C003C00u};

    // S-MMA for one 16-j group into sf
    auto s_group = [&](float sf[2][4], uint32_t kb0, int ntp) {
#pragma unroll
        for (int ks = 0; ks < 4; ks++) {
            unsigned kbf[4];
            ldsm4(kbf, kb0 + (uint32_t)((ntp*16*ALD + ks*8) * 4) + boffA);
            if (ks == 0) {
                mma_f16_z(sf[0], qf[0], kbf + 0);
                mma_f16_z(sf[1], qf[0], kbf + 2);
            } else {
                mma_f16(sf[0], qf[ks], kbf + 0);
                mma_f16(sf[1], qf[ks], kbf + 2);
            }
        }
    };

    // pipelined half-tile: S of ntp+1 issued before PV of ntp
    auto half_tile = [&](uint32_t kb0, uint32_t vb0) {
        float sf[2][4];
        s_group(sf, kb0, 0);
#pragma unroll
        for (int ntp = 0; ntp < 4; ntp++) {
            unsigned pf[4];
            pf[0] = ex2h2(sf[0][0] - rm0, sf[0][1] - rm0);
            pf[1] = ex2h2(sf[0][2] - rm1, sf[0][3] - rm1);
            pf[2] = ex2h2(sf[1][0] - rm0, sf[1][1] - rm0);
            pf[3] = ex2h2(sf[1][2] - rm1, sf[1][3] - rm1);
            // queue S of next group BEFORE PV so tensor stays fed during
            // the next iteration's scalar phase
            if (ntp < 3) s_group(sf, kb0, ntp + 1);
            mma_f16(rsum, pf, bones);
#pragma unroll
            for (int dtp = 0; dtp < 4; dtp++) {
                unsigned vb[4];
                ldsm4t(vb, vb0 + (uint32_t)((ntp*16*ALD) * 4) + dtp*32 + voffA);
                mma_f16(o[2*dtp + 0], pf, vb + 0);
                mma_f16(o[2*dtp + 1], pf, vb + 2);
            }
        }
    };

    const int njt = NTOK / 128;   // 16

    // ---- peeled jt=0: establish C from hf=0 (full-sf path), then fused hf=1
    {
        cp_wait1();
        __syncthreads();
        issue(2);
        cp_commit();
        const uint32_t stg = sbase;    // slot 0
        const uint32_t kb0 = stg, vb0 = stg + (uint32_t)(128*ALD)*4;

        float sf[8][4];
#pragma unroll
        for (int ks = 0; ks < 4; ks++) {
#pragma unroll
            for (int ntp = 0; ntp < 4; ntp++) {
                unsigned kbf[4];
                ldsm4(kbf, kb0 + (uint32_t)((ntp*16*ALD + ks*8) * 4) + boffA);
                if (ks == 0) {
                    mma_f16_z(sf[2*ntp + 0], qf[0], kbf + 0);
                    mma_f16_z(sf[2*ntp + 1], qf[0], kbf + 2);
                } else {
                    mma_f16(sf[2*ntp + 0], qf[ks], kbf + 0);
                    mma_f16(sf[2*ntp + 1], qf[ks], kbf + 2);
                }
            }
        }
        float mx0 = -1e30f, mx1 = -1e30f;
#pragma unroll
        for (int nt = 0; nt < 8; nt++) {
            mx0 = fmaxf(mx0, fmaxf(sf[nt][0], sf[nt][1]));
            mx1 = fmaxf(mx1, fmaxf(sf[nt][2], sf[nt][3]));
        }
        mx0 = fmaxf(mx0, __shfl_xor_sync(0xffffffffu, mx0, 1));
        mx0 = fmaxf(mx0, __shfl_xor_sync(0xffffffffu, mx0, 2));
        mx1 = fmaxf(mx1, __shfl_xor_sync(0xffffffffu, mx1, 1));
        mx1 = fmaxf(mx1, __shfl_xor_sync(0xffffffffu, mx1, 2));
        rm0 = mx0 + 4.0f;
        rm1 = mx1 + 4.0f;

#pragma unroll
        for (int ks = 0; ks < 4; ks++) {
            unsigned pf[4];
            pf[0] = ex2h2(sf[2*ks][0]     - rm0, sf[2*ks][1]     - rm0);
            pf[1] = ex2h2(sf[2*ks][2]     - rm1, sf[2*ks][3]     - rm1);
            pf[2] = ex2h2(sf[2*ks + 1][0] - rm0, sf[2*ks + 1][1] - rm0);
            pf[3] = ex2h2(sf[2*ks + 1][2] - rm1, sf[2*ks + 1][3] - rm1);
            mma_f16(rsum, pf, bones);
#pragma unroll
            for (int dtp = 0; dtp < 4; dtp++) {
                unsigned vb[4];
                ldsm4t(vb, vb0 + (uint32_t)((ks*16*ALD) * 4) + dtp*32 + voffA);
                mma_f16(o[2*dtp + 0], pf, vb + 0);
                mma_f16(o[2*dtp + 1], pf, vb + 2);
            }
        }

        // hf=1 of jt=0 via pipelined path
        half_tile(stg + (uint32_t)(64*ALD)*4, stg + (uint32_t)(192*ALD)*4);
    }

    // ---- jt = 1..15
    for (int jt = 1; jt < njt; jt++) {
        cp_wait1();
        __syncthreads();
        if (jt + 2 < njt) issue(jt + 2);
        cp_commit();
        const uint32_t stg = sbase + (uint32_t)((jt % 3) * AST_W) * 4;
        half_tile(stg,                          stg + (uint32_t)(128*ALD)*4);
        half_tile(stg + (uint32_t)(64*ALD)*4,   stg + (uint32_t)(192*ALD)*4);
    }

    const float inv0 = 1.f / rsum[0], inv1 = 1.f / rsum[2];
    const int b_ = bh >> 2, h_ = bh & 3;
    const int r0r = i0 + wrow + g, r1r = r0r + 8;
#pragma unroll
    for (int dt = 0; dt < 8; dt++) {
        const int d = h_ * 64 + dt*8 + 2*q;
        __half2 hv = __floats2half2_rn(o[dt][0] * inv0, o[dt][1] * inv0);
        *(__half2*)&O[((size_t)(b_ * NTOK + r0r)) * ldo + d] = hv;
        hv = __floats2half2_rn(o[dt][2] * inv1, o[dt][3] * inv1);
        *(__half2*)&O[((size_t)(b_ * NTOK + r1r)) * ldo + d] = hv;
    }
}

// ---------------------------------------------------------------------------
// Rowwise LayerNorm + exact GELU: h(fp32)[M,512] -> hg(fp16). 128 thr/row.
// ---------------------------------------------------------------------------
__global__ __launch_bounds__(128) void ln_gelu_kernel(
    const float* __restrict__ h0, const float* __restrict__ h1,
    __half* __restrict__ hg0, __half* __restrict__ hg1,
    const float* __restrict__ gamma, const float* __restrict__ beta)
{
    const float* row = (blockIdx.y ? h1 : h0) + (size_t)blockIdx.x * 512;
    __half* rowo = (blockIdx.y ? hg1 : hg0) + (size_t)blockIdx.x * 512;
    const int t = threadIdx.x;
    float4 v = *(const float4*)&row[t*4];
    __shared__ float red[8];

    float s = v.x + v.y + v.z + v.w;
#pragma unroll
    for (int off = 16; off > 0; off >>= 1) s += __shfl_xor_sync(0xffffffffu, s, off);
    if ((t & 31) == 0) red[t >> 5] = s;
    __syncthreads();
    const float mean = (red[0] + red[1] + red[2] + red[3]) * (1.0f/512.0f);

    const float d0 = v.x - mean, d1 = v.y - mean, d2 = v.z - mean, d3 = v.w - mean;
    float qv = d0*d0 + d1*d1 + d2*d2 + d3*d3;
#pragma unroll
    for (int off = 16; off > 0; off >>= 1) qv += __shfl_xor_sync(0xffffffffu, qv, off);
    if ((t & 31) == 0) red[4 + (t >> 5)] = qv;
    __syncthreads();
    const float var = (red[4] + red[5] + red[6] + red[7]) * (1.0f/512.0f);
    const float rstd = rsqrtf(var + 1e-5f);

    float4 g4 = *(const float4*)&gamma[t*4];
    float4 b4 = *(const float4*)&beta[t*4];
    float y[4];
    y[0] = d0*rstd*g4.x + b4.x;
    y[1] = d1*rstd*g4.y + b4.y;
    y[2] = d2*rstd*g4.z + b4.z;
    y[3] = d3*rstd*g4.w + b4.w;
#pragma unroll
    for (int i = 0; i < 4; i++)
        y[i] = 0.5f * y[i] * (1.0f + erff(y[i] * 0.70710678118654752f));
    uint2 u; u.x = h2u(y[0], y[1]); u.y = h2u(y[2], y[3]);
    *(uint2*)&rowo[t*4] = u;
}

// ---------------------------------------------------------------------------
extern "C" void kernel_launch(void* const* d_in, const int* in_sizes, int n_in,
                              void* d_out, int out_size)
{
    const float* x0    = (const float*)d_in[0];
    const float* x1    = (const float*)d_in[1];
    const float* Wqk   = (const float*)d_in[2];
    const float* bqk   = (const float*)d_in[3];
    const float* Wv    = (const float*)d_in[4];
    const float* bv    = (const float*)d_in[5];
    const float* Wp    = (const float*)d_in[6];
    const float* bp    = (const float*)d_in[7];
    const float* W1    = (const float*)d_in[8];
    const float* b1    = (const float*)d_in[9];
    const float* gamma = (const float*)d_in[10];
    const float* beta  = (const float*)d_in[11];
    const float* W2    = (const float*)d_in[12];
    const float* b2    = (const float*)d_in[13];
    float* out = (float*)d_out;

    __half *qk0, *qk1, *v0, *v1, *cat0, *cat1, *hg0, *hg1;
    __half *wqk, *wv, *wpT, *w1p, *wcat, *w2;
    float *h0, *h1, *b1p, *zeros;
    cudaGetSymbolAddress((void**)&qk0, g_qk0);
    cudaGetSymbolAddress((void**)&qk1, g_qk1);
    cudaGetSymbolAddress((void**)&v0,  g_v0);
    cudaGetSymbolAddress((void**)&v1,  g_v1);
    cudaGetSymbolAddress((void**)&cat0, g_cat0);
    cudaGetSymbolAddress((void**)&cat1, g_cat1);
    cudaGetSymbolAddress((void**)&h0,  g_h0);
    cudaGetSymbolAddress((void**)&h1,  g_h1);
    cudaGetSymbolAddress((void**)&hg0, g_hg0);
    cudaGetSymbolAddress((void**)&hg1, g_hg1);
    cudaGetSymbolAddress((void**)&wqk, g_wqk);
    cudaGetSymbolAddress((void**)&wv,  g_wv);
    cudaGetSymbolAddress((void**)&wpT, g_wpT);
    cudaGetSymbolAddress((void**)&w1p, g_w1p);
    cudaGetSymbolAddress((void**)&wcat, g_wcat);
    cudaGetSymbolAddress((void**)&w2,  g_w2);
    cudaGetSymbolAddress((void**)&b1p, g_b1p);
    cudaGetSymbolAddress((void**)&zeros, g_zeros);

    cudaFuncSetAttribute(gemm_kernel, cudaFuncAttributeMaxDynamicSharedMemorySize, GEMM_SMEM);
    cudaFuncSetAttribute(attn_kernel, cudaFuncAttributeMaxDynamicSharedMemorySize, ATT_SMEM);

    // 1) fp32 -> fp16 conversions (+ Wp transpose, W1 split)
    convert_kernel<<<dim3(2048, 1, 7), 256>>>(x0, x1, cat0, cat1,
        Wqk, Wv, Wp, W1, W2, wqk, wv, wpT, w1p, wcat, w2);

    // 1b) fold Wp into W1: wcat[:, 256:] = w1p @ Wp ; b1p = b1 + W1p @ bp
    gemm_kernel<<<dim3(4, 2, 1), 256, GEMM_SMEM>>>(
        w1p, w1p, 256, wpT, zeros, nullptr, nullptr,
        wcat, wcat, nullptr, nullptr, 512, 256, nullptr, nullptr,
        256, 2, EPI_PLAIN_H, 1.0f, 1.0f);
    b1p_kernel<<<512, 32>>>(W1, bp, b1, b1p);

    // 2) fused projections: y<2 -> Wqk (scaled) -> qk ; y>=2 -> Wv -> v
    gemm_kernel<<<dim3(MROWS/128, 4, 2), 256, GEMM_SMEM>>>(
        cat0, cat1, 512, wqk, bqk, wv, bv,
        qk0, qk1, v0, v1, 0, 0, nullptr, nullptr,
        FEATC, 2, EPI_HEAD_H, QK_SCALE_L2, 1.0f);

    // 3) bidirectional flash attention -> m into cat[:, 256:]
    attn_kernel<<<dim3(NTOK/128, BDIM*NHEADS, 2), 256, ATT_SMEM>>>(
        qk0, qk1, v0, v1, cat0 + 256, cat1 + 256, 512);

    // 4) MLP in-proj with fused weight (K=512) -> h fp32
    gemm_kernel<<<dim3(MROWS/128, 4, 2), 256, GEMM_SMEM>>>(
        cat0, cat1, 512, wcat, b1p, nullptr, nullptr,
        h0, h1, nullptr, nullptr, 512, 0, nullptr, nullptr,
        512, 4, EPI_PLAIN_F, 1.0f, 1.0f);

    // 5) LayerNorm + GELU -> hg fp16
    ln_gelu_kernel<<<dim3(MROWS, 2), 128>>>(h0, h1, hg0, hg1, gamma, beta);

    // 6) MLP out-proj + residual -> fp32 outputs
    gemm_kernel<<<dim3(MROWS/128, 2, 2), 256, GEMM_SMEM>>>(
        hg0, hg1, 512, w2, b2, nullptr, nullptr,
        out, out + (size_t)MROWS*FEATC, nullptr, nullptr, 256, 0, x0, x1,
        512, 2, EPI_RES, 1.0f, 1.0f);
}

// round 15
// speedup vs baseline: 1.0126x; 1.0126x over previous
#include <cuda_runtime.h>
#include <cuda_fp16.h>
#include <stdint.h>
#include <math.h>

#define BDIM   4
#define NTOK   2048
#define FEATC  256
#define HIDC   256
#define NHEADS 4
#define DHEAD  64
#define MROWS  (BDIM*NTOK)
#define QK_SCALE_L2 0.424660902f   // DH^-0.25 * sqrt(log2 e)

// ---------------- scratch ----------------
__device__ __half g_qk0[MROWS*HIDC];
__device__ __half g_qk1[MROWS*HIDC];
__device__ __half g_v0 [MROWS*HIDC];
__device__ __half g_v1 [MROWS*HIDC];
__device__ __half g_cat0[MROWS*2*FEATC];   // [x fp16 | m fp16]
__device__ __half g_cat1[MROWS*2*FEATC];
__device__ float  g_h0 [MROWS*2*FEATC];
__device__ float  g_h1 [MROWS*2*FEATC];
__device__ __half g_hg0[MROWS*2*FEATC];
__device__ __half g_hg1[MROWS*2*FEATC];
__device__ __half g_wqk[HIDC*FEATC];
__device__ __half g_wv [HIDC*FEATC];
__device__ __half g_wpT[HIDC*HIDC];          // Wp transposed [in][out]
__device__ __half g_w1p[2*FEATC*HIDC];       // W1 cols 256:512
__device__ __half g_wcat[2*FEATC*2*FEATC];   // [W1x | W1m]
__device__ __half g_w2 [FEATC*2*FEATC];
__device__ float  g_b1p[2*FEATC];            // b1 + W1p @ bp
__device__ float  g_zeros[256];              // never written (zero-init)

#define EPI_HEAD_H  0
#define EPI_PLAIN_H 1
#define EPI_PLAIN_F 2
#define EPI_RES     3

// ---------------- asm helpers ----------------
__device__ __forceinline__ void mma_f16(float* d, const unsigned* a, const unsigned* b) {
    asm volatile(
        "mma.sync.aligned.m16n8k16.row.col.f32.f16.f16.f32 "
        "{%0,%1,%2,%3}, {%4,%5,%6,%7}, {%8,%9}, {%0,%1,%2,%3};\n"
        : "+f"(d[0]), "+f"(d[1]), "+f"(d[2]), "+f"(d[3])
        : "r"(a[0]), "r"(a[1]), "r"(a[2]), "r"(a[3]), "r"(b[0]), "r"(b[1]));
}
// d = a*b + 0  (no accumulator read)
__device__ __forceinline__ void mma_f16_z(float* d, const unsigned* a, const unsigned* b) {
    asm volatile(
        "mma.sync.aligned.m16n8k16.row.col.f32.f16.f16.f32 "
        "{%0,%1,%2,%3}, {%4,%5,%6,%7}, {%8,%9}, {%10,%11,%12,%13};\n"
        : "=f"(d[0]), "=f"(d[1]), "=f"(d[2]), "=f"(d[3])
        : "r"(a[0]), "r"(a[1]), "r"(a[2]), "r"(a[3]), "r"(b[0]), "r"(b[1]),
          "f"(0.f), "f"(0.f), "f"(0.f), "f"(0.f));
}
// d = a*b + {c0,c0,c1,c1}  (folds the softmax reference into the S chain)
__device__ __forceinline__ void mma_f16_c(float* d, const unsigned* a, const unsigned* b,
                                          float c0, float c1) {
    asm volatile(
        "mma.sync.aligned.m16n8k16.row.col.f32.f16.f16.f32 "
        "{%0,%1,%2,%3}, {%4,%5,%6,%7}, {%8,%9}, {%10,%11,%12,%13};\n"
        : "=f"(d[0]), "=f"(d[1]), "=f"(d[2]), "=f"(d[3])
        : "r"(a[0]), "r"(a[1]), "r"(a[2]), "r"(a[3]), "r"(b[0]), "r"(b[1]),
          "f"(c0), "f"(c0), "f"(c1), "f"(c1));
}
__device__ __forceinline__ void ldsm4(unsigned* r, uint32_t a) {
    asm volatile("ldmatrix.sync.aligned.m8n8.x4.shared.b16 {%0,%1,%2,%3}, [%4];"
        : "=r"(r[0]), "=r"(r[1]), "=r"(r[2]), "=r"(r[3]) : "r"(a));
}
__device__ __forceinline__ void ldsm4t(unsigned* r, uint32_t a) {
    asm volatile("ldmatrix.sync.aligned.m8n8.x4.trans.shared.b16 {%0,%1,%2,%3}, [%4];"
        : "=r"(r[0]), "=r"(r[1]), "=r"(r[2]), "=r"(r[3]) : "r"(a));
}
__device__ __forceinline__ void cpa16(uint32_t dst, const void* src) {
    asm volatile("cp.async.cg.shared.global [%0], [%1], 16;" :: "r"(dst), "l"(src));
}
__device__ __forceinline__ void cp_commit() { asm volatile("cp.async.commit_group;"); }
__device__ __forceinline__ void cp_wait1() { asm volatile("cp.async.wait_group 1;"); }

__device__ __forceinline__ unsigned h2u(float x, float y) {
    __half2 h = __floats2half2_rn(x, y);
    return *reinterpret_cast<unsigned*>(&h);
}
__device__ __forceinline__ unsigned ex2h2(float x, float y) {
    __half2 h = __floats2half2_rn(x, y);
    unsigned u = *reinterpret_cast<unsigned*>(&h), r;
    asm volatile("ex2.approx.f16x2 %0, %1;" : "=r"(r) : "r"(u));
    return r;
}

// ---------------------------------------------------------------------------
// fp32 -> fp16 conversions; Wp transposed; W1 split into [W1x -> wcat | w1p]
// ---------------------------------------------------------------------------
__global__ __launch_bounds__(256) void convert_kernel(
    const float* __restrict__ x0, const float* __restrict__ x1,
    __half* __restrict__ cat0, __half* __restrict__ cat1,
    const float* __restrict__ Wqk, const float* __restrict__ Wv,
    const float* __restrict__ Wp, const float* __restrict__ W1, const float* __restrict__ W2,
    __half* __restrict__ wqk, __half* __restrict__ wv, __half* __restrict__ wpT,
    __half* __restrict__ w1p, __half* __restrict__ wcat, __half* __restrict__ w2)
{
    const int z = blockIdx.z;
    const long idx = (long)blockIdx.x * 256 + threadIdx.x;   // float4 units
    const float* src = nullptr; long cnt = 0;
    switch (z) {
        case 0: src = x0;  cnt = MROWS*FEATC/4; break;
        case 1: src = x1;  cnt = MROWS*FEATC/4; break;
        case 2: src = Wqk; cnt = HIDC*FEATC/4; break;
        case 3: src = Wv;  cnt = HIDC*FEATC/4; break;
        case 4: src = Wp;  cnt = HIDC*HIDC/4; break;
        case 5: src = W1;  cnt = 2*FEATC*512/4; break;
        case 6: src = W2;  cnt = FEATC*2*FEATC/4; break;
    }
    if (idx >= cnt) return;
    float4 v = *(const float4*)(src + idx*4);
    uint2 u; u.x = h2u(v.x, v.y); u.y = h2u(v.z, v.w);
    if (z <= 1) {
        __half* dst = z ? cat1 : cat0;
        long row = idx >> 6, c = (idx & 63) * 4;
        *(uint2*)(dst + row * 512 + c) = u;
    } else if (z == 2) {
        *(uint2*)(wqk + idx*4) = u;
    } else if (z == 3) {
        *(uint2*)(wv + idx*4) = u;
    } else if (z == 4) {
        long k = idx >> 6, i0 = (idx & 63) * 4;
        wpT[(i0+0)*HIDC + k] = __float2half_rn(v.x);
        wpT[(i0+1)*HIDC + k] = __float2half_rn(v.y);
        wpT[(i0+2)*HIDC + k] = __float2half_rn(v.z);
        wpT[(i0+3)*HIDC + k] = __float2half_rn(v.w);
    } else if (z == 5) {
        long o = idx >> 7, c = (idx & 127) * 4;
        if (c < 256) *(uint2*)(wcat + o * 512 + c) = u;
        else         *(uint2*)(w1p  + o * 256 + (c - 256)) = u;
    } else {
        *(uint2*)(w2 + idx*4) = u;
    }
}

// b1p[o] = b1[o] + sum_k W1[o][256+k] * bp[k]
__global__ __launch_bounds__(32) void b1p_kernel(
    const float* __restrict__ W1, const float* __restrict__ bp,
    const float* __restrict__ b1, float* __restrict__ b1p)
{
    const int o = blockIdx.x, lane = threadIdx.x;
    float s = 0.f;
#pragma unroll
    for (int i = 0; i < 8; i++) {
        int k = lane + i * 32;
        s += W1[(size_t)o * 512 + 256 + k] * bp[k];
    }
#pragma unroll
    for (int off = 16; off > 0; off >>= 1) s += __shfl_xor_sync(0xffffffffu, s, off);
    if (lane == 0) b1p[o] = b1[o] + s;
}

// ---------------------------------------------------------------------------
// GEMM: C = epi( A[M,K] @ W[N,K]^T + b ), fp16 in, fp32 acc.
// 3-stage cp.async ring, K-chunk 64. Tile 128x128x64; warp tile 32x64.
// (R11-R14 version, verbatim)
// ---------------------------------------------------------------------------
#define GLD  36
#define SST_W (256*GLD)
#define GEMM_SMEM (3*SST_W*4)         // 110592 B
__global__ __launch_bounds__(256, 2) void gemm_kernel(
    const __half* __restrict__ A0, const __half* __restrict__ A1, int lda,
    const __half* __restrict__ Wa, const float* __restrict__ biasa,
    const __half* __restrict__ Wb, const float* __restrict__ biasb,
    void* C0v, void* C1v, void* Cb0v, void* Cb1v, int ldc, int coloff,
    const float* __restrict__ R0, const float* __restrict__ R1,
    int K, int ytiles, int epi, float scalea, float scaleb)
{
    extern __shared__ unsigned sm[];
    const int t = threadIdx.x, lane = t & 31, wid = t >> 5;
    const int g = lane >> 2, q = lane & 3;
    const int wm = wid >> 1, wn = wid & 1;
    const int z = blockIdx.z;
    const bool second = (int)blockIdx.y >= ytiles;
    const int yy = second ? (blockIdx.y - ytiles) : blockIdx.y;
    const int m0g = blockIdx.x * 128, n0g = yy * 128;
    const __half* A = z ? A1 : A0;
    const __half* W = second ? Wb : Wa;
    const float* bias = second ? biasb : biasa;
    const float scale = second ? scaleb : scalea;
    void* Cv = second ? (z ? Cb1v : Cb0v) : (z ? C1v : C0v);
    const float* R = z ? R1 : R0;

    const uint32_t sb = (uint32_t)__cvta_generic_to_shared(sm);
    const uint32_t aoff = (((lane & 15) * GLD) + ((lane >> 4) << 2)) * 4;
    const uint32_t boff = (((lane & 7) + ((lane >> 4) << 3)) * GLD + (((lane >> 3) & 1) << 2)) * 4;

    const int nk = K >> 6;
    auto issue = [&](int kt) {
        const uint32_t stb = sb + (uint32_t)((kt % 3) * SST_W) * 4;
        const int kc = kt << 6;
#pragma unroll
        for (int i = 0; i < 8; i++) {
            const int idx = t + i * 256;
            const int row = idx >> 3, c = idx & 7;
            const uint32_t dst = stb + (uint32_t)(row * GLD + c * 4) * 4;
            const __half* src = (row < 128)
                ? (A + (size_t)(m0g + row) * lda + kc + c*8)
                : (W + (size_t)(n0g + row - 128) * K + kc + c*8);
            cpa16(dst, src);
        }
    };

    float acc[2][8][4];
#pragma unroll
    for (int mt = 0; mt < 2; mt++)
#pragma unroll
        for (int nt = 0; nt < 8; nt++)
#pragma unroll
            for (int i = 0; i < 4; i++) acc[mt][nt][i] = 0.f;

    issue(0); cp_commit();
    issue(1); cp_commit();

    for (int kt = 0; kt < nk; kt++) {
        cp_wait1();
        __syncthreads();
        if (kt + 2 < nk) issue(kt + 2);
        cp_commit();
        const uint32_t stb = sb + (uint32_t)((kt % 3) * SST_W) * 4;
#pragma unroll
        for (int ch = 0; ch < 4; ch++) {
            unsigned a[2][4], b[4][4];
#pragma unroll
            for (int mt = 0; mt < 2; mt++)
                ldsm4(a[mt], stb + (uint32_t)(((wm*32 + mt*16)*GLD + ch*8) * 4) + aoff);
#pragma unroll
            for (int bt = 0; bt < 4; bt++)
                ldsm4(b[bt], stb + (uint32_t)(((128 + wn*64 + bt*16)*GLD + ch*8) * 4) + boff);
#pragma unroll
            for (int mt = 0; mt < 2; mt++)
#pragma unroll
                for (int bt = 0; bt < 4; bt++) {
                    mma_f16(acc[mt][2*bt + 0], a[mt], b[bt] + 0);
                    mma_f16(acc[mt][2*bt + 1], a[mt], b[bt] + 2);
                }
        }
    }

#pragma unroll
    for (int mt = 0; mt < 2; mt++) {
#pragma unroll
        for (int nt = 0; nt < 8; nt++) {
            const int row = m0g + wm*32 + mt*16 + g;
            const int col = n0g + wn*64 + nt*8 + 2*q;
            const float b0 = bias[col], b1 = bias[col + 1];
#pragma unroll
            for (int hh = 0; hh < 2; hh++) {
                const int rr = row + hh * 8;
                float vx = (acc[mt][nt][hh*2+0] + b0) * scale;
                float vy = (acc[mt][nt][hh*2+1] + b1) * scale;
                if (epi == EPI_HEAD_H) {
                    const int b_ = rr >> 11, nn = rr & (NTOK - 1);
                    const int h_ = col >> 6, dd = col & 63;
                    __half2 hv = __floats2half2_rn(vx, vy);
                    *(__half2*)((__half*)Cv + (((size_t)(b_*NHEADS + h_))*NTOK + nn)*DHEAD + dd) = hv;
                } else if (epi == EPI_PLAIN_H) {
                    __half2 hv = __floats2half2_rn(vx, vy);
                    *(__half2*)((__half*)Cv + (size_t)rr * ldc + coloff + col) = hv;
                } else if (epi == EPI_RES) {
                    float2 rv = *(const float2*)&R[(size_t)rr * ldc + col];
                    float2 v2; v2.x = vx + rv.x; v2.y = vy + rv.y;
                    *(float2*)((float*)Cv + (size_t)rr * ldc + col) = v2;
                } else {
                    float2 v2; v2.x = vx; v2.y = vy;
                    *(float2*)((float*)Cv + (size_t)rr * ldc + col) = v2;
                }
            }
        }
    }
}

// ---------------------------------------------------------------------------
// Flash attention, fixed-reference softmax. Convoy-breaking version:
//  - reference folded into S-MMA initial accumulator (no FADD phase)
//  - odd warps process the two 64-j halves in reverse order so scalar and
//    tensor phases of different warps overlap within each jt.
// KV tile 128 j/stage, Q staged via ring slot 2. Output into cat[:, 256:].
// ---------------------------------------------------------------------------
#define ALD  36
#define AST_W (256*ALD)
#define ATT_SMEM (3*AST_W*4)            // 110592 B

__global__ __launch_bounds__(256, 2) void attn_kernel(
    const __half* __restrict__ qk0, const __half* __restrict__ qk1,
    const __half* __restrict__ v0,  const __half* __restrict__ v1,
    __half* __restrict__ O0, __half* __restrict__ O1, int ldo)
{
    extern __shared__ unsigned smw[];

    const __half *Q, *Kp, *Vp; __half* O;
    if (blockIdx.z == 0) { Q = qk0; Kp = qk1; Vp = v1; O = O0; }
    else                 { Q = qk1; Kp = qk0; Vp = v0; O = O1; }

    const int bh = blockIdx.y;
    const int i0 = blockIdx.x * 128;
    const __half* Qb = Q  + (size_t)bh * NTOK * DHEAD;
    const __half* Kb = Kp + (size_t)bh * NTOK * DHEAD;
    const __half* Vb = Vp + (size_t)bh * NTOK * DHEAD;

    const int t = threadIdx.x, lane = t & 31, wid = t >> 5;
    const int g = lane >> 2, q = lane & 3;
    const int wrow = wid * 16;

    const uint32_t sbase = (uint32_t)__cvta_generic_to_shared(smw);
    const uint32_t aoffA = (((lane & 15) * ALD) + ((lane >> 4) << 2)) * 4;
    const uint32_t boffA = (((lane & 7) + ((lane >> 4) << 3)) * ALD + (((lane >> 3) & 1) << 2)) * 4;
    const uint32_t voffA = ((lane & 15) * ALD) * 4 + ((lane >> 4) << 4);

    const int kvrow = t >> 3, kvch = t & 7;
    auto issue = [&](int jt) {
        const uint32_t stb = sbase + (uint32_t)((jt % 3) * AST_W) * 4;
        const int j0 = jt << 7;
#pragma unroll
        for (int i = 0; i < 8; i++) {
            const int idx = kvrow + i * 32;
            const __half* src = (idx < 128)
                ? (Kb + (size_t)(j0 + idx) * DHEAD + kvch*8)
                : (Vb + (size_t)(j0 + idx - 128) * DHEAD + kvch*8);
            cpa16(stb + (uint32_t)(idx*ALD + kvch*4)*4, src);
        }
    };

    issue(0); cp_commit();
    issue(1); cp_commit();

    // stage Q tile through ring slot 2
#pragma unroll
    for (int i = 0; i < 4; i++) {
        int id = t + i * 256;
        int row = id >> 3, c8 = (id & 7) * 8;
        uint4 u = *(const uint4*)(Qb + (size_t)(i0 + row) * DHEAD + c8);
        *(uint4*)&smw[2*AST_W + row * ALD + (c8 >> 1)] = u;
    }
    __syncthreads();
    unsigned qf[4][4];
#pragma unroll
    for (int ks = 0; ks < 4; ks++)
        ldsm4(qf[ks], sbase + (uint32_t)((2*AST_W + wrow * ALD + ks * 8) * 4) + aoffA);

    float o[8][4];
#pragma unroll
    for (int dt = 0; dt < 8; dt++)
#pragma unroll
        for (int i = 0; i < 4; i++) o[dt][i] = 0.f;
    float rm0 = 0.f, rm1 = 0.f;              // fixed softmax reference
    float rsum[4] = {0.f, 0.f, 0.f, 0.f};    // persistent P@ones accumulator

    const unsigned bones[2] = {0x3C003C00u, 0x3C003C00u};

    // half-tile: per 16-j group, S-chain starts at {-rm} (reference folded in)
    auto half_tile = [&](uint32_t kb0, uint32_t vb0) {
#pragma unroll
        for (int ntp = 0; ntp < 4; ntp++) {
            float sf[2][4];
#pragma unroll
            for (int ks = 0; ks < 4; ks++) {
                unsigned kbf[4];
                ldsm4(kbf, kb0 + (uint32_t)((ntp*16*ALD + ks*8) * 4) + boffA);
                if (ks == 0) {
                    mma_f16_c(sf[0], qf[0], kbf + 0, -rm0, -rm1);
                    mma_f16_c(sf[1], qf[0], kbf + 2, -rm0, -rm1);
                } else {
                    mma_f16(sf[0], qf[ks], kbf + 0);
                    mma_f16(sf[1], qf[ks], kbf + 2);
                }
            }
            unsigned pf[4];
            pf[0] = ex2h2(sf[0][0], sf[0][1]);
            pf[1] = ex2h2(sf[0][2], sf[0][3]);
            pf[2] = ex2h2(sf[1][0], sf[1][1]);
            pf[3] = ex2h2(sf[1][2], sf[1][3]);
            mma_f16(rsum, pf, bones);
#pragma unroll
            for (int dtp = 0; dtp < 4; dtp++) {
                unsigned vb[4];
                ldsm4t(vb, vb0 + (uint32_t)((ntp*16*ALD) * 4) + dtp*32 + voffA);
                mma_f16(o[2*dtp + 0], pf, vb + 0);
                mma_f16(o[2*dtp + 1], pf, vb + 2);
            }
        }
    };

    const int njt = NTOK / 128;   // 16
    const bool rev = (wid & 1);   // warp-parity phase stagger

    // ---- peeled jt=0: establish C from hf=0 (full-sf path), then hf=1
    {
        cp_wait1();
        __syncthreads();
        issue(2);
        cp_commit();
        const uint32_t stg = sbase;    // slot 0
        const uint32_t kb0 = stg, vb0 = stg + (uint32_t)(128*ALD)*4;

        float sf[8][4];
#pragma unroll
        for (int ks = 0; ks < 4; ks++) {
#pragma unroll
            for (int ntp = 0; ntp < 4; ntp++) {
                unsigned kbf[4];
                ldsm4(kbf, kb0 + (uint32_t)((ntp*16*ALD + ks*8) * 4) + boffA);
                if (ks == 0) {
                    mma_f16_z(sf[2*ntp + 0], qf[0], kbf + 0);
                    mma_f16_z(sf[2*ntp + 1], qf[0], kbf + 2);
                } else {
                    mma_f16(sf[2*ntp + 0], qf[ks], kbf + 0);
                    mma_f16(sf[2*ntp + 1], qf[ks], kbf + 2);
                }
            }
        }
        float mx0 = -1e30f, mx1 = -1e30f;
#pragma unroll
        for (int nt = 0; nt < 8; nt++) {
            mx0 = fmaxf(mx0, fmaxf(sf[nt][0], sf[nt][1]));
            mx1 = fmaxf(mx1, fmaxf(sf[nt][2], sf[nt][3]));
        }
        mx0 = fmaxf(mx0, __shfl_xor_sync(0xffffffffu, mx0, 1));
        mx0 = fmaxf(mx0, __shfl_xor_sync(0xffffffffu, mx0, 2));
        mx1 = fmaxf(mx1, __shfl_xor_sync(0xffffffffu, mx1, 1));
        mx1 = fmaxf(mx1, __shfl_xor_sync(0xffffffffu, mx1, 2));
        rm0 = mx0 + 4.0f;
        rm1 = mx1 + 4.0f;

#pragma unroll
        for (int ks = 0; ks < 4; ks++) {
            unsigned pf[4];
            pf[0] = ex2h2(sf[2*ks][0]     - rm0, sf[2*ks][1]     - rm0);
            pf[1] = ex2h2(sf[2*ks][2]     - rm1, sf[2*ks][3]     - rm1);
            pf[2] = ex2h2(sf[2*ks + 1][0] - rm0, sf[2*ks + 1][1] - rm0);
            pf[3] = ex2h2(sf[2*ks + 1][2] - rm1, sf[2*ks + 1][3] - rm1);
            mma_f16(rsum, pf, bones);
#pragma unroll
            for (int dtp = 0; dtp < 4; dtp++) {
                unsigned vb[4];
                ldsm4t(vb, vb0 + (uint32_t)((ks*16*ALD) * 4) + dtp*32 + voffA);
                mma_f16(o[2*dtp + 0], pf, vb + 0);
                mma_f16(o[2*dtp + 1], pf, vb + 2);
            }
        }

        // hf=1 of jt=0
        half_tile(stg + (uint32_t)(64*ALD)*4, stg + (uint32_t)(192*ALD)*4);
    }

    // ---- jt = 1..15, halves ordered by warp parity (convoy breaking)
    for (int jt = 1; jt < njt; jt++) {
        cp_wait1();
        __syncthreads();
        if (jt + 2 < njt) issue(jt + 2);
        cp_commit();
        const uint32_t stg = sbase + (uint32_t)((jt % 3) * AST_W) * 4;
        const uint32_t kA = stg,                        vA = stg + (uint32_t)(128*ALD)*4;
        const uint32_t kB = stg + (uint32_t)(64*ALD)*4, vB = stg + (uint32_t)(192*ALD)*4;
        if (rev) { half_tile(kB, vB); half_tile(kA, vA); }
        else     { half_tile(kA, vA); half_tile(kB, vB); }
    }

    const float inv0 = 1.f / rsum[0], inv1 = 1.f / rsum[2];
    const int b_ = bh >> 2, h_ = bh & 3;
    const int r0r = i0 + wrow + g, r1r = r0r + 8;
#pragma unroll
    for (int dt = 0; dt < 8; dt++) {
        const int d = h_ * 64 + dt*8 + 2*q;
        __half2 hv = __floats2half2_rn(o[dt][0] * inv0, o[dt][1] * inv0);
        *(__half2*)&O[((size_t)(b_ * NTOK + r0r)) * ldo + d] = hv;
        hv = __floats2half2_rn(o[dt][2] * inv1, o[dt][3] * inv1);
        *(__half2*)&O[((size_t)(b_ * NTOK + r1r)) * ldo + d] = hv;
    }
}

// ---------------------------------------------------------------------------
// Rowwise LayerNorm + exact GELU: h(fp32)[M,512] -> hg(fp16). 128 thr/row.
// ---------------------------------------------------------------------------
__global__ __launch_bounds__(128) void ln_gelu_kernel(
    const float* __restrict__ h0, const float* __restrict__ h1,
    __half* __restrict__ hg0, __half* __restrict__ hg1,
    const float* __restrict__ gamma, const float* __restrict__ beta)
{
    const float* row = (blockIdx.y ? h1 : h0) + (size_t)blockIdx.x * 512;
    __half* rowo = (blockIdx.y ? hg1 : hg0) + (size_t)blockIdx.x * 512;
    const int t = threadIdx.x;
    float4 v = *(const float4*)&row[t*4];
    __shared__ float red[8];

    float s = v.x + v.y + v.z + v.w;
#pragma unroll
    for (int off = 16; off > 0; off >>= 1) s += __shfl_xor_sync(0xffffffffu, s, off);
    if ((t & 31) == 0) red[t >> 5] = s;
    __syncthreads();
    const float mean = (red[0] + red[1] + red[2] + red[3]) * (1.0f/512.0f);

    const float d0 = v.x - mean, d1 = v.y - mean, d2 = v.z - mean, d3 = v.w - mean;
    float qv = d0*d0 + d1*d1 + d2*d2 + d3*d3;
#pragma unroll
    for (int off = 16; off > 0; off >>= 1) qv += __shfl_xor_sync(0xffffffffu, qv, off);
    if ((t & 31) == 0) red[4 + (t >> 5)] = qv;
    __syncthreads();
    const float var = (red[4] + red[5] + red[6] + red[7]) * (1.0f/512.0f);
    const float rstd = rsqrtf(var + 1e-5f);

    float4 g4 = *(const float4*)&gamma[t*4];
    float4 b4 = *(const float4*)&beta[t*4];
    float y[4];
    y[0] = d0*rstd*g4.x + b4.x;
    y[1] = d1*rstd*g4.y + b4.y;
    y[2] = d2*rstd*g4.z + b4.z;
    y[3] = d3*rstd*g4.w + b4.w;
#pragma unroll
    for (int i = 0; i < 4; i++)
        y[i] = 0.5f * y[i] * (1.0f + erff(y[i] * 0.70710678118654752f));
    uint2 u; u.x = h2u(y[0], y[1]); u.y = h2u(y[2], y[3]);
    *(uint2*)&rowo[t*4] = u;
}

// ---------------------------------------------------------------------------
extern "C" void kernel_launch(void* const* d_in, const int* in_sizes, int n_in,
                              void* d_out, int out_size)
{
    const float* x0    = (const float*)d_in[0];
    const float* x1    = (const float*)d_in[1];
    const float* Wqk   = (const float*)d_in[2];
    const float* bqk   = (const float*)d_in[3];
    const float* Wv    = (const float*)d_in[4];
    const float* bv    = (const float*)d_in[5];
    const float* Wp    = (const float*)d_in[6];
    const float* bp    = (const float*)d_in[7];
    const float* W1    = (const float*)d_in[8];
    const float* b1    = (const float*)d_in[9];
    const float* gamma = (const float*)d_in[10];
    const float* beta  = (const float*)d_in[11];
    const float* W2    = (const float*)d_in[12];
    const float* b2    = (const float*)d_in[13];
    float* out = (float*)d_out;

    __half *qk0, *qk1, *v0, *v1, *cat0, *cat1, *hg0, *hg1;
    __half *wqk, *wv, *wpT, *w1p, *wcat, *w2;
    float *h0, *h1, *b1p, *zeros;
    cudaGetSymbolAddress((void**)&qk0, g_qk0);
    cudaGetSymbolAddress((void**)&qk1, g_qk1);
    cudaGetSymbolAddress((void**)&v0,  g_v0);
    cudaGetSymbolAddress((void**)&v1,  g_v1);
    cudaGetSymbolAddress((void**)&cat0, g_cat0);
    cudaGetSymbolAddress((void**)&cat1, g_cat1);
    cudaGetSymbolAddress((void**)&h0,  g_h0);
    cudaGetSymbolAddress((void**)&h1,  g_h1);
    cudaGetSymbolAddress((void**)&hg0, g_hg0);
    cudaGetSymbolAddress((void**)&hg1, g_hg1);
    cudaGetSymbolAddress((void**)&wqk, g_wqk);
    cudaGetSymbolAddress((void**)&wv,  g_wv);
    cudaGetSymbolAddress((void**)&wpT, g_wpT);
    cudaGetSymbolAddress((void**)&w1p, g_w1p);
    cudaGetSymbolAddress((void**)&wcat, g_wcat);
    cudaGetSymbolAddress((void**)&w2,  g_w2);
    cudaGetSymbolAddress((void**)&b1p, g_b1p);
    cudaGetSymbolAddress((void**)&zeros, g_zeros);

    cudaFuncSetAttribute(gemm_kernel, cudaFuncAttributeMaxDynamicSharedMemorySize, GEMM_SMEM);
    cudaFuncSetAttribute(attn_kernel, cudaFuncAttributeMaxDynamicSharedMemorySize, ATT_SMEM);

    // 1) fp32 -> fp16 conversions (+ Wp transpose, W1 split)
    convert_kernel<<<dim3(2048, 1, 7), 256>>>(x0, x1, cat0, cat1,
        Wqk, Wv, Wp, W1, W2, wqk, wv, wpT, w1p, wcat, w2);

    // 1b) fold Wp into W1: wcat[:, 256:] = w1p @ Wp ; b1p = b1 + W1p @ bp
    gemm_kernel<<<dim3(4, 2, 1), 256, GEMM_SMEM>>>(
        w1p, w1p, 256, wpT, zeros, nullptr, nullptr,
        wcat, wcat, nullptr, nullptr, 512, 256, nullptr, nullptr,
        256, 2, EPI_PLAIN_H, 1.0f, 1.0f);
    b1p_kernel<<<512, 32>>>(W1, bp, b1, b1p);

    // 2) fused projections: y<2 -> Wqk (scaled) -> qk ; y>=2 -> Wv -> v
    gemm_kernel<<<dim3(MROWS/128, 4, 2), 256, GEMM_SMEM>>>(
        cat0, cat1, 512, wqk, bqk, wv, bv,
        qk0, qk1, v0, v1, 0, 0, nullptr, nullptr,
        FEATC, 2, EPI_HEAD_H, QK_SCALE_L2, 1.0f);

    // 3) bidirectional flash attention -> m into cat[:, 256:]
    attn_kernel<<<dim3(NTOK/128, BDIM*NHEADS, 2), 256, ATT_SMEM>>>(
        qk0, qk1, v0, v1, cat0 + 256, cat1 + 256, 512);

    // 4) MLP in-proj with fused weight (K=512) -> h fp32
    gemm_kernel<<<dim3(MROWS/128, 4, 2), 256, GEMM_SMEM>>>(
        cat0, cat1, 512, wcat, b1p, nullptr, nullptr,
        h0, h1, nullptr, nullptr, 512, 0, nullptr, nullptr,
        512, 4, EPI_PLAIN_F, 1.0f, 1.0f);

    // 5) LayerNorm + GELU -> hg fp16
    ln_gelu_kernel<<<dim3(MROWS, 2), 128>>>(h0, h1, hg0, hg1, gamma, beta);

    // 6) MLP out-proj + residual -> fp32 outputs
    gemm_kernel<<<dim3(MROWS/128, 2, 2), 256, GEMM_SMEM>>>(
        hg0, hg1, 512, w2, b2, nullptr, nullptr,
        out, out + (size_t)MROWS*FEATC, nullptr, nullptr, 256, 0, x0, x1,
        512, 2, EPI_RES, 1.0f, 1.0f);
}